// round 6
// baseline (speedup 1.0000x reference)
#include <cuda_runtime.h>
#include <cuda_bf16.h>
#include <math.h>

// Problem constants
#define B_DIM 16
#define S_DIM 4096
#define F_DIM 512
#define NCLS 10
#define HID 64
#define ODIM 128

#define COLS_PER_CTA 2
#define NTHREADS 512
#define ROWS_PER_THREAD (S_DIM / (NTHREADS / COLS_PER_CTA))   // 16
#define TAB_SLOTS 8192          // per-column hash slots (<=4096 distinct -> LF 0.5)
#define EMPTY_SLOT 0xFFFFFFFFu  // canonicalized values never have this bit pattern

// Shared memory (dynamic), bytes:
// phase 1: [0, 65536)       2 hash tables of 8192 u32
//          [65536, 69632)   y labels for this batch as u8 (4096)
// phase 2 overlay (inside tables region, after __syncthreads):
//          [0, 2048)        red: 16 warps x 32 floats (2 cols x 15 stats, padded)
//          [2048, 2176)     tot: 2 cols x 16 stats
//          [2304, 2352)     stats6: 2 cols x 6
//          [2432, 2944)     h: 2 cols x 64
//          [4096, 36864)    w2 staged (64x128 f32)
#define OFF_TABLES   0
#define OFF_Y8       65536
#define OFF_RED      0
#define OFF_TOT      2048
#define OFF_STATS    2304
#define OFF_H        2432
#define OFF_W2       4096
#define SMEM_BYTES   69632

__device__ float g_class_counts[B_DIM * NCLS];

__global__ void class_count_kernel(const int* __restrict__ y) {
    __shared__ int hist[NCLS];
    int b = blockIdx.x;
    if (threadIdx.x < NCLS) hist[threadIdx.x] = 0;
    __syncthreads();
    for (int i = threadIdx.x; i < S_DIM; i += blockDim.x)
        atomicAdd(&hist[y[b * S_DIM + i]], 1);
    __syncthreads();
    if (threadIdx.x < NCLS) g_class_counts[b * NCLS + threadIdx.x] = (float)hist[threadIdx.x];
}

// Exact distinct-count insert: Fibonacci hash, CAS-first, linear probe on rare
// collisions. Unique total = number of CAS winners -> race-order invariant.
__device__ __forceinline__ void hins(unsigned int* __restrict__ tab, float v, float& uniq) {
    unsigned int bits = __float_as_uint(v);
    bits = (v == 0.0f) ? 0u : bits;                 // -0 -> +0 canonicalization
    unsigned int slot = (bits * 2654435761u) >> 19; // top 13 bits
    unsigned int cur = atomicCAS(tab + slot, EMPTY_SLOT, bits);
    while (cur != EMPTY_SLOT && cur != bits) {
        slot = (slot + 1) & (TAB_SLOTS - 1);
        cur = atomicCAS(tab + slot, EMPTY_SLOT, bits);
    }
    if (cur == EMPTY_SLOT) uniq += 1.0f;
}

__global__ __launch_bounds__(NTHREADS, 3)
void stats_mlp_kernel(const float* __restrict__ X,
                      const int*   __restrict__ y,
                      const float* __restrict__ w1,
                      const float* __restrict__ b1,
                      const float* __restrict__ w2,
                      const float* __restrict__ b2,
                      float* __restrict__ out) {
    extern __shared__ char smem[];
    unsigned int* tables = (unsigned int*)(smem + OFF_TABLES);
    unsigned char* y8 = (unsigned char*)(smem + OFF_Y8);

    const int tid  = threadIdx.x;
    const int lane = tid & 31;
    const int wid  = tid >> 5;
    const int g  = blockIdx.x;       // feature group 0..255
    const int b  = blockIdx.y;       // batch 0..15
    const int f0 = g * COLS_PER_CTA;

    // init hash tables (16384 words) with EMPTY (vectorized)
    {
        uint4* tv = (uint4*)tables;
        uint4 e = make_uint4(EMPTY_SLOT, EMPTY_SLOT, EMPTY_SLOT, EMPTY_SLOT);
        #pragma unroll
        for (int i = 0; i < (COLS_PER_CTA * TAB_SLOTS / 4) / NTHREADS; i++)
            tv[tid + i * NTHREADS] = e;
    }
    // stage y as bytes
    #pragma unroll
    for (int i = 0; i < S_DIM / NTHREADS; i++)
        y8[tid + i * NTHREADS] = (unsigned char)y[b * S_DIM + tid + i * NTHREADS];
    __syncthreads();

    const int col = tid & 1;         // lane pairs read 8 contiguous bytes
    const int r0  = tid >> 1;        // 0..255

    float sum = 0.f, sumsq = 0.f, sumabs = 0.f, maxabs = 0.f, nanc = 0.f;
    float uniq = 0.f;
    float csum[NCLS - 1];            // class 9 derived as sum - others
    #pragma unroll
    for (int c = 0; c < NCLS - 1; c++) csum[c] = 0.f;

    unsigned int* tab = tables + col * TAB_SLOTS;
    const float* Xb = X + ((size_t)b * S_DIM) * F_DIM + f0 + col;

    #pragma unroll 4
    for (int i = 0; i < ROWS_PER_THREAD; i++) {
        const int r = r0 + 256 * i;
        float x = __ldg(&Xb[(size_t)r * F_DIM]);
        int yv = (int)y8[r];
        bool isn = isnan(x);
        float v = isn ? 0.0f : x;
        nanc += isn ? 1.0f : 0.0f;
        sum += v;
        sumsq = fmaf(v, v, sumsq);
        float a = fabsf(v);
        sumabs += a;
        maxabs = fmaxf(maxabs, a);
        #pragma unroll
        for (int c = 0; c < NCLS - 1; c++)
            csum[c] += (yv == c) ? v : 0.0f;

        hins(tab, v, uniq);
    }
    __syncthreads();   // tables & y8 done; tables region reusable as overlay

    float* red    = (float*)(smem + OFF_RED);    // [16][32]: [warp][col*15+stat]
    float* tot    = (float*)(smem + OFF_TOT);    // [2][16]
    float* stats6 = (float*)(smem + OFF_STATS);
    float* hsm    = (float*)(smem + OFF_H);
    float* w2s    = (float*)(smem + OFF_W2);

    // ---- warp butterfly reduce 15 stats; stop at offset 2 to keep col parity ----
    {
        float st[15];
        st[0] = sum; st[1] = sumsq; st[2] = sumabs; st[3] = maxabs;
        st[4] = nanc; st[5] = uniq;
        #pragma unroll
        for (int c = 0; c < NCLS - 1; c++) st[6 + c] = csum[c];
        #pragma unroll
        for (int k = 0; k < 15; k++) {
            float v = st[k];
            #pragma unroll
            for (int off = 16; off >= 2; off >>= 1) {
                float o = __shfl_xor_sync(0xFFFFFFFFu, v, off);
                v = (k == 3) ? fmaxf(v, o) : v + o;
            }
            st[k] = v;
        }
        if (lane < 2) {
            #pragma unroll
            for (int k = 0; k < 15; k++) red[wid * 32 + lane * 15 + k] = st[k];
        }
    }
    __syncthreads();

    // ---- cross-warp totals: threads 0..29 each own one (col, stat) ----
    if (tid < 30) {
        int c = tid / 15, s = tid % 15;
        float v = red[0 * 32 + c * 15 + s];
        #pragma unroll
        for (int w = 1; w < 16; w++) {
            float o = red[w * 32 + c * 15 + s];
            v = (s == 3) ? fmaxf(v, o) : v + o;
        }
        tot[c * 16 + s] = v;
    }
    // stage w2 into smem (all threads; disjoint region)
    {
        const float4* w2v = (const float4*)w2;
        float4* w2d = (float4*)w2s;
        #pragma unroll
        for (int i = 0; i < (HID * ODIM / 4) / NTHREADS; i++)
            w2d[tid + i * NTHREADS] = w2v[tid + i * NTHREADS];
    }
    __syncthreads();

    // ---- per-column final stats (threads 0..1) ----
    if (tid < COLS_PER_CTA) {
        const float Sf = (float)S_DIM;
        float tsum    = tot[tid * 16 + 0];
        float tsumsq  = tot[tid * 16 + 1];
        float tsumabs = tot[tid * 16 + 2];
        float tmaxabs = tot[tid * 16 + 3];
        float tnan    = tot[tid * 16 + 4];
        float tuniq   = tot[tid * 16 + 5];
        float gmean = tsum / Sf;
        float var = fmaxf(tsumsq / Sf - gmean * gmean, 0.0f);
        float cs9 = tsum;
        #pragma unroll
        for (int c = 0; c < NCLS - 1; c++) cs9 -= tot[tid * 16 + 6 + c];
        float between = 0.0f;
        #pragma unroll
        for (int c = 0; c < NCLS; c++) {
            float cnt = g_class_counts[b * NCLS + c];
            float cs = (c < NCLS - 1) ? tot[tid * 16 + 6 + c] : cs9;
            float cm = cs / fmaxf(cnt, 1.0f);
            float d = cm - gmean;
            between = fmaf(cnt, d * d, between);
        }
        between /= Sf;
        stats6[tid * 6 + 0] = between / fmaxf(var, 1e-6f);
        stats6[tid * 6 + 1] = tnan / Sf;
        stats6[tid * 6 + 2] = tuniq / Sf;
        stats6[tid * 6 + 3] = var;
        stats6[tid * 6 + 4] = tsumabs / Sf;
        stats6[tid * 6 + 5] = tmaxabs;
    }
    __syncthreads();

    // ---- MLP layer 1: h = gelu_exact(stats6 @ w1 + b1), 2 cols x 64 ----
    if (tid < COLS_PER_CTA * HID) {
        int ch = tid >> 6, j = tid & 63;
        float acc = b1[j];
        #pragma unroll
        for (int i = 0; i < 6; i++)
            acc = fmaf(stats6[ch * 6 + i], w1[i * HID + j], acc);
        hsm[ch * HID + j] = 0.5f * acc * (1.0f + erff(acc * 0.70710678118654752f));
    }
    __syncthreads();

    // ---- MLP layer 2: out = h @ w2 + b2, 2 cols x 128 (one output/thread) ----
    if (tid < COLS_PER_CTA * ODIM) {
        int ch = tid >> 7, k = tid & 127;
        float acc = b2[k];
        #pragma unroll
        for (int j = 0; j < HID; j++)
            acc = fmaf(hsm[ch * HID + j], w2s[j * ODIM + k], acc);
        out[(((size_t)b * F_DIM) + f0 + ch) * ODIM + k] = acc;
    }
}

extern "C" void kernel_launch(void* const* d_in, const int* in_sizes, int n_in,
                              void* d_out, int out_size) {
    const float* X  = (const float*)d_in[0];
    const int*   y  = (const int*)d_in[1];
    const float* w1 = (const float*)d_in[2];
    const float* b1 = (const float*)d_in[3];
    const float* w2 = (const float*)d_in[4];
    const float* b2 = (const float*)d_in[5];
    float* out = (float*)d_out;

    cudaFuncSetAttribute(stats_mlp_kernel,
                         cudaFuncAttributeMaxDynamicSharedMemorySize, SMEM_BYTES);

    class_count_kernel<<<B_DIM, 256>>>(y);
    dim3 grid(F_DIM / COLS_PER_CTA, B_DIM);
    stats_mlp_kernel<<<grid, NTHREADS, SMEM_BYTES>>>(X, y, w1, b1, w2, b2, out);
}